// round 12
// baseline (speedup 1.0000x reference)
#include <cuda_runtime.h>

#define BB   1024
#define TT   512
#define IN   6
#define HH   64
#define GG   256
#define RR   8
#define NTH  512
#define NCTA (BB / RR)

// smem offsets (floats)
#define OFF_WHH1 0            // quad layout: W4[(kq*GG+g)*4 + (k&3)], 16384
#define OFF_WA   16384        // Whh0 staging (pair layout) 16384
#define OFF_WB   32768        // Wih1 staging (pair layout) 16384
#define OFF_WX   49152        // Wih0 (pair) 1536
#define OFF_B0   50688        // 256
#define OFF_B1   50944        // 256
#define OFF_GSH1 51200        // 2048  [g][r]
#define OFF_GSHP 53248        // 2048
#define OFF_HT0  55296        // 2 bufs x 512
#define OFF_HT1  56320        // 2 bufs x 512
#define OFF_XT   57344        // 2 bufs x 128
#define SMEM_FLOATS 57600
#define SMEM_BYTES  (SMEM_FLOATS * 4)   // 230400

typedef unsigned long long u64;

__device__ __forceinline__ u64 ffma2(u64 a, u64 b, u64 c) {
    u64 d;
    asm("fma.rn.f32x2 %0, %1, %2, %3;" : "=l"(d) : "l"(a), "l"(b), "l"(c));
    return d;
}
__device__ __forceinline__ float hsum2(u64 a) {
    union { u64 u; float2 f; } cvt; cvt.u = a;
    return cvt.f.x + cvt.f.y;
}
__device__ __forceinline__ float fex2(float x) {
    float y; asm("ex2.approx.ftz.f32 %0, %1;" : "=f"(y) : "f"(x)); return y;
}
__device__ __forceinline__ float frcp(float x) {
    float y; asm("rcp.approx.ftz.f32 %0, %1;" : "=f"(y) : "f"(x)); return y;
}
__device__ __forceinline__ float sigmoidf_(float x) {
    return frcp(1.0f + fex2(-1.4426950408889634f * x));
}
__device__ __forceinline__ float tanhf_(float x) {
    return fmaf(2.0f, frcp(1.0f + fex2(-2.8853900817779268f * x)), -1.0f);
}
// line-merged h index for k-pair p: pairs p and p+16 share a 128B line
__device__ __forceinline__ int lidx(int p) {
    return (p & 15) * 32 + (p >> 4) * 16;
}

__global__ void __launch_bounds__(NTH, 1)
lstm_net_kernel(const float* __restrict__ x,
                const float* __restrict__ Wih0, const float* __restrict__ Whh0,
                const float* __restrict__ bih0, const float* __restrict__ bhh0,
                const float* __restrict__ Wih1, const float* __restrict__ Whh1,
                const float* __restrict__ bih1, const float* __restrict__ bhh1,
                const float* __restrict__ Wfc1, const float* __restrict__ bfc1,
                const float* __restrict__ Wfc2, const float* __restrict__ bfc2,
                float* __restrict__ out) {
    extern __shared__ float s[];
    float* Whh1s = s + OFF_WHH1;
    float* WAs   = s + OFF_WA;
    float* WBs   = s + OFF_WB;
    float* WXs   = s + OFF_WX;
    float* b0s   = s + OFF_B0;
    float* b1s   = s + OFF_B1;
    float* gsh1  = s + OFF_GSH1;
    float* gshP  = s + OFF_GSHP;
    float* hT0   = s + OFF_HT0;
    float* hT1   = s + OFF_HT1;
    float* xT    = s + OFF_XT;

    const int tid  = threadIdx.x;
    const int lane = tid & 31;
    const int w    = tid >> 5;
    const int gl   = lane & 15;
    const int half = lane >> 4;      // k-half: kp in [half*16, half*16+16)
    const int g    = w * 16 + gl;    // gate column
    const int b0_  = blockIdx.x * RR;

    // ---- Stage weights ----
    for (int i = tid; i < HH * GG; i += NTH) {
        int gg_ = i >> 6;
        int k   = i & 63;
        int dp  = ((k >> 1) * GG + gg_) * 2 + (k & 1);          // pair layout
        WAs[dp] = Whh0[i];
        WBs[dp] = Wih1[i];
        Whh1s[((k >> 2) * GG + gg_) * 4 + (k & 3)] = Whh1[i];   // quad layout
    }
    for (int i = tid; i < IN * GG; i += NTH) {
        int gg_ = i / IN;
        int k   = i - gg_ * IN;
        WXs[((k >> 1) * GG + gg_) * 2 + (k & 1)] = Wih0[i];
    }
    if (tid < GG) {
        b0s[tid] = bih0[tid] + bhh0[tid];
        b1s[tid] = bih1[tid] + bhh1[tid];
    }
    for (int i = tid; i < 2048; i += NTH) hT0[i] = 0.0f;   // zeros hT0+hT1

    // x staging role (tid < 48)
    const int xk = tid >> 3;
    const int xr = tid & 7;
    const float* xgp = x + (size_t)(b0_ + xr) * TT * IN + xk;
    float* xslot0 = xT + (xk >> 1) * 32 + xr * 2 + (xk & 1);
    float xreg = 0.0f;
    if (tid < 48) xreg = xgp[0];                           // x_0

    // update role
    const int uj = tid >> 3;      // 0..63
    const int ur = tid & 7;       // 0..7
    const int hix = lidx(uj >> 1) + ur * 2 + (uj & 1);
    float c0 = 0.0f, c1 = 0.0f;

    __syncthreads();

    // ---- Fill weight registers: Whh0 + Wih1 (this lane's k-half, col g) ----
    u64 wpr[16], w1r[16];
#pragma unroll
    for (int i = 0; i < 16; i++) {
        const int off = ((half * 16 + i) * GG + g) * 2;
        wpr[i] = *(const u64*)(WAs + off);
        w1r[i] = *(const u64*)(WBs + off);
    }
    u64 wxr[3] = {0ULL, 0ULL, 0ULL};
    if (half == 0) {
#pragma unroll
        for (int p = 0; p < 3; p++)
            wxr[p] = *(const u64*)(WXs + (p * GG + g) * 2);
    }
    const float bias0 = b0s[g];
    const float bias1 = b1s[g];

    // hoisted pointers
    const float* whp  = Whh1s + ((half * 8) * GG + g) * 4;  // quad: 2 pairs / LDS.128
    float* gsh1w = gsh1 + g * 8;
    float* gshPw = gshP + g * 8;
    const float* g1u = gsh1 + uj * 8 + ur;
    const float* gPu = gshP + uj * 8 + ur;

    // publish x_0 into xT buf1 (scratch)
    if (tid < 48) xslot0[128] = xreg;
    __syncthreads();

    // ================= PROLOGUE: gates0_0 = bias0 + Wih0 @ x_0 =================
    {
        u64 accP[8] = {0,0,0,0,0,0,0,0};
        if (half == 0) {
#pragma unroll
            for (int p = 0; p < 3; p++) {
                const float* xp = xT + 128 + p * 32;
                ulonglong2 A = *(const ulonglong2*)(xp);
                ulonglong2 B = *(const ulonglong2*)(xp + 4);
                ulonglong2 C = *(const ulonglong2*)(xp + 8);
                ulonglong2 D = *(const ulonglong2*)(xp + 12);
                accP[0] = ffma2(A.x, wxr[p], accP[0]);
                accP[1] = ffma2(A.y, wxr[p], accP[1]);
                accP[2] = ffma2(B.x, wxr[p], accP[2]);
                accP[3] = ffma2(B.y, wxr[p], accP[3]);
                accP[4] = ffma2(C.x, wxr[p], accP[4]);
                accP[5] = ffma2(C.y, wxr[p], accP[5]);
                accP[6] = ffma2(D.x, wxr[p], accP[6]);
                accP[7] = ffma2(D.y, wxr[p], accP[7]);
            }
        }
        float sPv[8];
#pragma unroll
        for (int r = 0; r < 8; r++) sPv[r] = hsum2(accP[r]);
#pragma unroll
        for (int r = 0; r < 8; r++) sPv[r] += __shfl_down_sync(0xffffffffu, sPv[r], 16);
        if (half == 0) {
            *(float4*)(gshPw) =
                make_float4(sPv[0] + bias0, sPv[1] + bias0, sPv[2] + bias0, sPv[3] + bias0);
            *(float4*)(gshPw + 4) =
                make_float4(sPv[4] + bias0, sPv[5] + bias0, sPv[6] + bias0, sPv[7] + bias0);
        }
        if (tid < 48) xreg = xgp[1 * IN];   // x_1
        __syncthreads();

        float gi = sigmoidf_(gPu[0]);
        float gf = sigmoidf_(gPu[64 * 8]);
        float gc = tanhf_  (gPu[128 * 8]);
        float go = sigmoidf_(gPu[192 * 8]);
        c0 = fmaf(gf, c0, gi * gc);
        hT0[hix] = go * tanhf_(c0);                 // buf 0
        if (tid < 48) xslot0[0] = xreg;             // buf 0
        __syncthreads();
    }

    // ================= MAIN LOOP =================
    for (int t = 0; t < TT; t++) {
        const int rb = t & 1;
        const int wb = rb ^ 1;

        if (tid < 48 && t + 2 < TT)
            xreg = xgp[(size_t)(t + 2) * IN];

        u64 acc1[8] = {0,0,0,0,0,0,0,0};   // layer-1 gates (t)
        u64 accP[8] = {0,0,0,0,0,0,0,0};   // layer-0 gates (t+1)

        const float* h0b = hT0 + rb * 512 + half * 16;
        const float* h1b = hT1 + rb * 512 + half * 16;
#pragma unroll
        for (int i = 0; i < 8; i++) {
            // Whh1 quad: 2 pairs per LDS.128
            ulonglong2 wh = *(const ulonglong2*)(whp + i * (GG * 4));
            const u64 w1a = w1r[2 * i],     wpa = wpr[2 * i];
            const u64 w1b = w1r[2 * i + 1], wpb = wpr[2 * i + 1];

            // h0 pair 2i: feeds two register weight streams
            const float* p0 = h0b + (2 * i) * 32;
            ulonglong2 A = *(const ulonglong2*)(p0);
            ulonglong2 B = *(const ulonglong2*)(p0 + 4);
            ulonglong2 C = *(const ulonglong2*)(p0 + 8);
            ulonglong2 D = *(const ulonglong2*)(p0 + 12);
            acc1[0] = ffma2(A.x, w1a, acc1[0]);  accP[0] = ffma2(A.x, wpa, accP[0]);
            acc1[1] = ffma2(A.y, w1a, acc1[1]);  accP[1] = ffma2(A.y, wpa, accP[1]);
            acc1[2] = ffma2(B.x, w1a, acc1[2]);  accP[2] = ffma2(B.x, wpa, accP[2]);
            acc1[3] = ffma2(B.y, w1a, acc1[3]);  accP[3] = ffma2(B.y, wpa, accP[3]);
            acc1[4] = ffma2(C.x, w1a, acc1[4]);  accP[4] = ffma2(C.x, wpa, accP[4]);
            acc1[5] = ffma2(C.y, w1a, acc1[5]);  accP[5] = ffma2(C.y, wpa, accP[5]);
            acc1[6] = ffma2(D.x, w1a, acc1[6]);  accP[6] = ffma2(D.x, wpa, accP[6]);
            acc1[7] = ffma2(D.y, w1a, acc1[7]);  accP[7] = ffma2(D.y, wpa, accP[7]);

            // h0 pair 2i+1
            const float* p1 = h0b + (2 * i + 1) * 32;
            A = *(const ulonglong2*)(p1);
            B = *(const ulonglong2*)(p1 + 4);
            C = *(const ulonglong2*)(p1 + 8);
            D = *(const ulonglong2*)(p1 + 12);
            acc1[0] = ffma2(A.x, w1b, acc1[0]);  accP[0] = ffma2(A.x, wpb, accP[0]);
            acc1[1] = ffma2(A.y, w1b, acc1[1]);  accP[1] = ffma2(A.y, wpb, accP[1]);
            acc1[2] = ffma2(B.x, w1b, acc1[2]);  accP[2] = ffma2(B.x, wpb, accP[2]);
            acc1[3] = ffma2(B.y, w1b, acc1[3]);  accP[3] = ffma2(B.y, wpb, accP[3]);
            acc1[4] = ffma2(C.x, w1b, acc1[4]);  accP[4] = ffma2(C.x, wpb, accP[4]);
            acc1[5] = ffma2(C.y, w1b, acc1[5]);  accP[5] = ffma2(C.y, wpb, accP[5]);
            acc1[6] = ffma2(D.x, w1b, acc1[6]);  accP[6] = ffma2(D.x, wpb, accP[6]);
            acc1[7] = ffma2(D.y, w1b, acc1[7]);  accP[7] = ffma2(D.y, wpb, accP[7]);

            // h1 pair 2i
            const float* q0 = h1b + (2 * i) * 32;
            A = *(const ulonglong2*)(q0);
            B = *(const ulonglong2*)(q0 + 4);
            C = *(const ulonglong2*)(q0 + 8);
            D = *(const ulonglong2*)(q0 + 12);
            acc1[0] = ffma2(A.x, wh.x, acc1[0]);
            acc1[1] = ffma2(A.y, wh.x, acc1[1]);
            acc1[2] = ffma2(B.x, wh.x, acc1[2]);
            acc1[3] = ffma2(B.y, wh.x, acc1[3]);
            acc1[4] = ffma2(C.x, wh.x, acc1[4]);
            acc1[5] = ffma2(C.y, wh.x, acc1[5]);
            acc1[6] = ffma2(D.x, wh.x, acc1[6]);
            acc1[7] = ffma2(D.y, wh.x, acc1[7]);

            // h1 pair 2i+1
            const float* q1 = h1b + (2 * i + 1) * 32;
            A = *(const ulonglong2*)(q1);
            B = *(const ulonglong2*)(q1 + 4);
            C = *(const ulonglong2*)(q1 + 8);
            D = *(const ulonglong2*)(q1 + 12);
            acc1[0] = ffma2(A.x, wh.y, acc1[0]);
            acc1[1] = ffma2(A.y, wh.y, acc1[1]);
            acc1[2] = ffma2(B.x, wh.y, acc1[2]);
            acc1[3] = ffma2(B.y, wh.y, acc1[3]);
            acc1[4] = ffma2(C.x, wh.y, acc1[4]);
            acc1[5] = ffma2(C.y, wh.y, acc1[5]);
            acc1[6] = ffma2(D.x, wh.y, acc1[6]);
            acc1[7] = ffma2(D.y, wh.y, acc1[7]);
        }
        if (half == 0) {      // accP += Wih0 @ x_{t+1}
            const float* xb = xT + rb * 128;
#pragma unroll
            for (int p = 0; p < 3; p++) {
                const float* xp = xb + p * 32;
                ulonglong2 A = *(const ulonglong2*)(xp);
                ulonglong2 B = *(const ulonglong2*)(xp + 4);
                ulonglong2 C = *(const ulonglong2*)(xp + 8);
                ulonglong2 D = *(const ulonglong2*)(xp + 12);
                accP[0] = ffma2(A.x, wxr[p], accP[0]);
                accP[1] = ffma2(A.y, wxr[p], accP[1]);
                accP[2] = ffma2(B.x, wxr[p], accP[2]);
                accP[3] = ffma2(B.y, wxr[p], accP[3]);
                accP[4] = ffma2(C.x, wxr[p], accP[4]);
                accP[5] = ffma2(C.y, wxr[p], accP[5]);
                accP[6] = ffma2(D.x, wxr[p], accP[6]);
                accP[7] = ffma2(D.y, wxr[p], accP[7]);
            }
        }

        // combine k-halves in-warp: s1 -> half0 (shfl_down), sP -> half1 (shfl_up)
        float s1v[8], sPv[8];
#pragma unroll
        for (int r = 0; r < 8; r++) { s1v[r] = hsum2(acc1[r]); sPv[r] = hsum2(accP[r]); }
#pragma unroll
        for (int r = 0; r < 8; r++) {
            s1v[r] += __shfl_down_sync(0xffffffffu, s1v[r], 16);
            sPv[r] += __shfl_up_sync(0xffffffffu, sPv[r], 16);
        }
        if (half == 0) {
            *(float4*)(gsh1w) =
                make_float4(s1v[0] + bias1, s1v[1] + bias1, s1v[2] + bias1, s1v[3] + bias1);
            *(float4*)(gsh1w + 4) =
                make_float4(s1v[4] + bias1, s1v[5] + bias1, s1v[6] + bias1, s1v[7] + bias1);
        } else {
            *(float4*)(gshPw) =
                make_float4(sPv[0] + bias0, sPv[1] + bias0, sPv[2] + bias0, sPv[3] + bias0);
            *(float4*)(gshPw + 4) =
                make_float4(sPv[4] + bias0, sPv[5] + bias0, sPv[6] + bias0, sPv[7] + bias0);
        }
        __syncthreads();

        // ---------- PHASE 2: both cell updates ----------
        {
            float gi = sigmoidf_(g1u[0]);
            float gf = sigmoidf_(g1u[64 * 8]);
            float gc = tanhf_  (g1u[128 * 8]);
            float go = sigmoidf_(g1u[192 * 8]);
            c1 = fmaf(gf, c1, gi * gc);
            hT1[wb * 512 + hix] = go * tanhf_(c1);            // h1_t
        }
        {
            float gi = sigmoidf_(gPu[0]);
            float gf = sigmoidf_(gPu[64 * 8]);
            float gc = tanhf_  (gPu[128 * 8]);
            float go = sigmoidf_(gPu[192 * 8]);
            c0 = fmaf(gf, c0, gi * gc);
            hT0[wb * 512 + hix] = go * tanhf_(c0);            // h0_{t+1}
        }
        if (tid < 48 && t + 2 < TT)
            xslot0[wb * 128] = xreg;                          // x_{t+2}
        __syncthreads();
    }

    // ================= FC head: h1_{TT-1} lives in buffer TT&1 = 0 =================
    if (tid < 256) {
        const int row = tid >> 5;
        const int m   = tid & 31;
        float acc2 = bfc1[m];
#pragma unroll 8
        for (int k = 0; k < HH; k++) {
            int p = k >> 1;
            float hv = hT1[(TT & 1) * 512 + lidx(p) + row * 2 + (k & 1)];
            acc2 = fmaf(hv, Wfc1[m * HH + k], acc2);
        }
        acc2 = fmaxf(acc2, 0.0f) * Wfc2[m];
#pragma unroll
        for (int off = 16; off > 0; off >>= 1)
            acc2 += __shfl_down_sync(0xffffffffu, acc2, off);
        if (m == 0)
            out[b0_ + row] = acc2 + bfc2[0];
    }
}

extern "C" void kernel_launch(void* const* d_in, const int* in_sizes, int n_in,
                              void* d_out, int out_size) {
    const float* x    = (const float*)d_in[0];
    const float* Wih0 = (const float*)d_in[1];
    const float* Whh0 = (const float*)d_in[2];
    const float* bih0 = (const float*)d_in[3];
    const float* bhh0 = (const float*)d_in[4];
    const float* Wih1 = (const float*)d_in[5];
    const float* Whh1 = (const float*)d_in[6];
    const float* bih1 = (const float*)d_in[7];
    const float* bhh1 = (const float*)d_in[8];
    const float* Wfc1 = (const float*)d_in[9];
    const float* bfc1 = (const float*)d_in[10];
    const float* Wfc2 = (const float*)d_in[11];
    const float* bfc2 = (const float*)d_in[12];
    float* out = (float*)d_out;

    cudaFuncSetAttribute(lstm_net_kernel,
                         cudaFuncAttributeMaxDynamicSharedMemorySize, SMEM_BYTES);
    lstm_net_kernel<<<NCTA, NTH, SMEM_BYTES>>>(
        x, Wih0, Whh0, bih0, bhh0, Wih1, Whh1, bih1, bhh1,
        Wfc1, bfc1, Wfc2, bfc2, out);
}

// round 13
// speedup vs baseline: 1.0644x; 1.0644x over previous
#include <cuda_runtime.h>

#define BB   1024
#define TT   512
#define IN   6
#define HH   64
#define GG   256
#define RR   8
#define NTH  512
#define NCTA (BB / RR)

// smem offsets (floats)
#define OFF_WHH1 0            // pair layout: W2[(kp*GG+g)*2 + (k&1)], 16384
#define OFF_WA   16384        // Whh0 staging (pair layout) 16384
#define OFF_WB   32768        // Wih1 staging (pair layout) 16384
#define OFF_WX   49152        // Wih0 (pair) 1536
#define OFF_B0   50688        // 256
#define OFF_B1   50944        // 256
#define OFF_GSH1 51200        // 2048  [g][r]
#define OFF_GSHP 53248        // 2048
#define OFF_HT0  55296        // 2 bufs x 512
#define OFF_HT1  56320        // 2 bufs x 512
#define OFF_XT   57344        // 2 bufs x 128
#define SMEM_FLOATS 57600
#define SMEM_BYTES  (SMEM_FLOATS * 4)   // 230400

typedef unsigned long long u64;

__device__ __forceinline__ u64 ffma2(u64 a, u64 b, u64 c) {
    u64 d;
    asm("fma.rn.f32x2 %0, %1, %2, %3;" : "=l"(d) : "l"(a), "l"(b), "l"(c));
    return d;
}
__device__ __forceinline__ float hsum2(u64 a) {
    union { u64 u; float2 f; } cvt; cvt.u = a;
    return cvt.f.x + cvt.f.y;
}
__device__ __forceinline__ float fex2(float x) {
    float y; asm("ex2.approx.ftz.f32 %0, %1;" : "=f"(y) : "f"(x)); return y;
}
__device__ __forceinline__ float frcp(float x) {
    float y; asm("rcp.approx.ftz.f32 %0, %1;" : "=f"(y) : "f"(x)); return y;
}
__device__ __forceinline__ float sigmoidf_(float x) {
    return frcp(1.0f + fex2(-1.4426950408889634f * x));
}
__device__ __forceinline__ float tanhf_(float x) {
    return fmaf(2.0f, frcp(1.0f + fex2(-2.8853900817779268f * x)), -1.0f);
}
// line-merged h index for k-pair p: pairs p and p+16 share a 128B line
__device__ __forceinline__ int lidx(int p) {
    return (p & 15) * 32 + (p >> 4) * 16;
}

__global__ void __launch_bounds__(NTH, 1)
lstm_net_kernel(const float* __restrict__ x,
                const float* __restrict__ Wih0, const float* __restrict__ Whh0,
                const float* __restrict__ bih0, const float* __restrict__ bhh0,
                const float* __restrict__ Wih1, const float* __restrict__ Whh1,
                const float* __restrict__ bih1, const float* __restrict__ bhh1,
                const float* __restrict__ Wfc1, const float* __restrict__ bfc1,
                const float* __restrict__ Wfc2, const float* __restrict__ bfc2,
                float* __restrict__ out) {
    extern __shared__ float s[];
    float* Whh1s = s + OFF_WHH1;
    float* WAs   = s + OFF_WA;
    float* WBs   = s + OFF_WB;
    float* WXs   = s + OFF_WX;
    float* b0s   = s + OFF_B0;
    float* b1s   = s + OFF_B1;
    float* gsh1  = s + OFF_GSH1;
    float* gshP  = s + OFF_GSHP;
    float* hT0   = s + OFF_HT0;
    float* hT1   = s + OFF_HT1;
    float* xT    = s + OFF_XT;

    const int tid  = threadIdx.x;
    const int lane = tid & 31;
    const int w    = tid >> 5;
    const int gl   = lane & 15;
    const int half = lane >> 4;      // k-half: kp in [half*16, half*16+16)
    const int g    = w * 16 + gl;    // gate column
    const int b0_  = blockIdx.x * RR;

    // ---- Stage weights (all pair layout) ----
    for (int i = tid; i < HH * GG; i += NTH) {
        int gg_ = i >> 6;
        int k   = i & 63;
        int dp  = ((k >> 1) * GG + gg_) * 2 + (k & 1);
        WAs[dp]   = Whh0[i];
        WBs[dp]   = Wih1[i];
        Whh1s[dp] = Whh1[i];
    }
    for (int i = tid; i < IN * GG; i += NTH) {
        int gg_ = i / IN;
        int k   = i - gg_ * IN;
        WXs[((k >> 1) * GG + gg_) * 2 + (k & 1)] = Wih0[i];
    }
    if (tid < GG) {
        b0s[tid] = bih0[tid] + bhh0[tid];
        b1s[tid] = bih1[tid] + bhh1[tid];
    }
    for (int i = tid; i < 2048; i += NTH) hT0[i] = 0.0f;   // zeros hT0+hT1

    // x staging role (tid < 48)
    const int xk = tid >> 3;
    const int xr = tid & 7;
    const float* xgp = x + (size_t)(b0_ + xr) * TT * IN + xk;
    float* xslot0 = xT + (xk >> 1) * 32 + xr * 2 + (xk & 1);
    float xreg = 0.0f;
    if (tid < 48) xreg = xgp[0];                           // x_0

    // update role
    const int uj = tid >> 3;      // 0..63
    const int ur = tid & 7;       // 0..7
    const int hix = lidx(uj >> 1) + ur * 2 + (uj & 1);
    float c0 = 0.0f, c1 = 0.0f;

    __syncthreads();

    // ---- Fill weight registers: Whh0 + Wih1 (this lane's k-half, col g) ----
    u64 wpr[16], w1r[16];
#pragma unroll
    for (int i = 0; i < 16; i++) {
        const int off = ((half * 16 + i) * GG + g) * 2;
        wpr[i] = *(const u64*)(WAs + off);
        w1r[i] = *(const u64*)(WBs + off);
    }
    u64 wxr[3] = {0ULL, 0ULL, 0ULL};
    if (half == 0) {
#pragma unroll
        for (int p = 0; p < 3; p++)
            wxr[p] = *(const u64*)(WXs + (p * GG + g) * 2);
    }
    const float bias0 = b0s[g];
    const float bias1 = b1s[g];

    // ---- hoisted pointers (all per-step arithmetic becomes imm offsets / XOR) ----
    const float* whp   = Whh1s + (half * 16 * GG + g) * 2;  // + i*GG*2 (imm)
    float* gsh1w = gsh1 + g * 8;
    float* gshPw = gshP + g * 8;
    const float* g1u = gsh1 + uj * 8 + ur;
    const float* gPu = gshP + uj * 8 + ur;
    const char* ph0 = (const char*)(hT0 + half * 16);       // + rbB
    const char* ph1 = (const char*)(hT1 + half * 16);
    const char* pxb = (const char*)xT;                      // + rbB/4... x buf is 128 floats = 512B
    char* ph1w = (char*)(hT1 + hix);
    char* ph0w = (char*)(hT0 + hix);
    char* pxw  = (char*)xslot0;

    // publish x_0 into xT buf1 (scratch)
    if (tid < 48) xslot0[128] = xreg;
    __syncthreads();

    // ================= PROLOGUE: gates0_0 = bias0 + Wih0 @ x_0 =================
    {
        u64 accP[8] = {0,0,0,0,0,0,0,0};
        if (half == 0) {
#pragma unroll
            for (int p = 0; p < 3; p++) {
                const float* xp = xT + 128 + p * 32;
                ulonglong2 A = *(const ulonglong2*)(xp);
                ulonglong2 B = *(const ulonglong2*)(xp + 4);
                ulonglong2 C = *(const ulonglong2*)(xp + 8);
                ulonglong2 D = *(const ulonglong2*)(xp + 12);
                accP[0] = ffma2(A.x, wxr[p], accP[0]);
                accP[1] = ffma2(A.y, wxr[p], accP[1]);
                accP[2] = ffma2(B.x, wxr[p], accP[2]);
                accP[3] = ffma2(B.y, wxr[p], accP[3]);
                accP[4] = ffma2(C.x, wxr[p], accP[4]);
                accP[5] = ffma2(C.y, wxr[p], accP[5]);
                accP[6] = ffma2(D.x, wxr[p], accP[6]);
                accP[7] = ffma2(D.y, wxr[p], accP[7]);
            }
        }
        float sPv[8];
#pragma unroll
        for (int r = 0; r < 8; r++) sPv[r] = hsum2(accP[r]);
#pragma unroll
        for (int r = 0; r < 8; r++) sPv[r] += __shfl_down_sync(0xffffffffu, sPv[r], 16);
        if (half == 0) {
            *(float4*)(gshPw) =
                make_float4(sPv[0] + bias0, sPv[1] + bias0, sPv[2] + bias0, sPv[3] + bias0);
            *(float4*)(gshPw + 4) =
                make_float4(sPv[4] + bias0, sPv[5] + bias0, sPv[6] + bias0, sPv[7] + bias0);
        }
        if (tid < 48) xreg = xgp[1 * IN];   // x_1
        __syncthreads();

        float gi = sigmoidf_(gPu[0]);
        float gf = sigmoidf_(gPu[64 * 8]);
        float gc = tanhf_  (gPu[128 * 8]);
        float go = sigmoidf_(gPu[192 * 8]);
        c0 = fmaf(gf, c0, gi * gc);
        hT0[hix] = go * tanhf_(c0);                 // buf 0
        if (tid < 48) xslot0[0] = xreg;             // buf 0
        __syncthreads();
    }

    // ================= MAIN LOOP =================
    int rbB = 0;                 // read-buffer byte offset (h bufs: 0/2048)
    for (int t = 0; t < TT; t++) {
        const int wbB = rbB ^ 2048;

        if (tid < 48 && t + 2 < TT)
            xreg = xgp[(size_t)(t + 2) * IN];

        u64 acc1[8] = {0,0,0,0,0,0,0,0};   // layer-1 gates (t)
        u64 accP[8] = {0,0,0,0,0,0,0,0};   // layer-0 gates (t+1)

        const float* h0b = (const float*)(ph0 + rbB);
        const float* h1b = (const float*)(ph1 + rbB);
#pragma unroll
        for (int i = 0; i < 16; i++) {
            // h0 pair: feeds two register weight streams
            const float* p0 = h0b + i * 32;
            ulonglong2 A = *(const ulonglong2*)(p0);
            ulonglong2 B = *(const ulonglong2*)(p0 + 4);
            ulonglong2 C = *(const ulonglong2*)(p0 + 8);
            ulonglong2 D = *(const ulonglong2*)(p0 + 12);
            const u64 w1 = w1r[i], wp = wpr[i];
            acc1[0] = ffma2(A.x, w1, acc1[0]);  accP[0] = ffma2(A.x, wp, accP[0]);
            acc1[1] = ffma2(A.y, w1, acc1[1]);  accP[1] = ffma2(A.y, wp, accP[1]);
            acc1[2] = ffma2(B.x, w1, acc1[2]);  accP[2] = ffma2(B.x, wp, accP[2]);
            acc1[3] = ffma2(B.y, w1, acc1[3]);  accP[3] = ffma2(B.y, wp, accP[3]);
            acc1[4] = ffma2(C.x, w1, acc1[4]);  accP[4] = ffma2(C.x, wp, accP[4]);
            acc1[5] = ffma2(C.y, w1, acc1[5]);  accP[5] = ffma2(C.y, wp, accP[5]);
            acc1[6] = ffma2(D.x, w1, acc1[6]);  accP[6] = ffma2(D.x, wp, accP[6]);
            acc1[7] = ffma2(D.y, w1, acc1[7]);  accP[7] = ffma2(D.y, wp, accP[7]);

            // h1 pair: Whh1 from smem (pair layout, imm offset)
            const u64 wh = *(const u64*)(whp + i * (GG * 2));
            const float* p1 = h1b + i * 32;
            ulonglong2 E = *(const ulonglong2*)(p1);
            ulonglong2 F = *(const ulonglong2*)(p1 + 4);
            ulonglong2 Gq = *(const ulonglong2*)(p1 + 8);
            ulonglong2 Hq = *(const ulonglong2*)(p1 + 12);
            acc1[0] = ffma2(E.x,  wh, acc1[0]);
            acc1[1] = ffma2(E.y,  wh, acc1[1]);
            acc1[2] = ffma2(F.x,  wh, acc1[2]);
            acc1[3] = ffma2(F.y,  wh, acc1[3]);
            acc1[4] = ffma2(Gq.x, wh, acc1[4]);
            acc1[5] = ffma2(Gq.y, wh, acc1[5]);
            acc1[6] = ffma2(Hq.x, wh, acc1[6]);
            acc1[7] = ffma2(Hq.y, wh, acc1[7]);
        }
        if (half == 0) {      // accP += Wih0 @ x_{t+1}   (x buf: 512B ping-pong)
            const float* xb = (const float*)(pxb + (rbB >> 2));
#pragma unroll
            for (int p = 0; p < 3; p++) {
                const float* xp = xb + p * 32;
                ulonglong2 A = *(const ulonglong2*)(xp);
                ulonglong2 B = *(const ulonglong2*)(xp + 4);
                ulonglong2 C = *(const ulonglong2*)(xp + 8);
                ulonglong2 D = *(const ulonglong2*)(xp + 12);
                accP[0] = ffma2(A.x, wxr[p], accP[0]);
                accP[1] = ffma2(A.y, wxr[p], accP[1]);
                accP[2] = ffma2(B.x, wxr[p], accP[2]);
                accP[3] = ffma2(B.y, wxr[p], accP[3]);
                accP[4] = ffma2(C.x, wxr[p], accP[4]);
                accP[5] = ffma2(C.y, wxr[p], accP[5]);
                accP[6] = ffma2(D.x, wxr[p], accP[6]);
                accP[7] = ffma2(D.y, wxr[p], accP[7]);
            }
        }

        // combine k-halves in-warp, half0 stores final gates
        float s1v[8], sPv[8];
#pragma unroll
        for (int r = 0; r < 8; r++) { s1v[r] = hsum2(acc1[r]); sPv[r] = hsum2(accP[r]); }
#pragma unroll
        for (int r = 0; r < 8; r++) {
            s1v[r] += __shfl_down_sync(0xffffffffu, s1v[r], 16);
            sPv[r] += __shfl_down_sync(0xffffffffu, sPv[r], 16);
        }
        if (half == 0) {
            *(float4*)(gsh1w) =
                make_float4(s1v[0] + bias1, s1v[1] + bias1, s1v[2] + bias1, s1v[3] + bias1);
            *(float4*)(gsh1w + 4) =
                make_float4(s1v[4] + bias1, s1v[5] + bias1, s1v[6] + bias1, s1v[7] + bias1);
            *(float4*)(gshPw) =
                make_float4(sPv[0] + bias0, sPv[1] + bias0, sPv[2] + bias0, sPv[3] + bias0);
            *(float4*)(gshPw + 4) =
                make_float4(sPv[4] + bias0, sPv[5] + bias0, sPv[6] + bias0, sPv[7] + bias0);
        }
        __syncthreads();

        // ---------- PHASE 2: both cell updates ----------
        {
            float gi = sigmoidf_(g1u[0]);
            float gf = sigmoidf_(g1u[64 * 8]);
            float gc = tanhf_  (g1u[128 * 8]);
            float go = sigmoidf_(g1u[192 * 8]);
            c1 = fmaf(gf, c1, gi * gc);
            *(float*)(ph1w + wbB) = go * tanhf_(c1);          // h1_t
        }
        {
            float gi = sigmoidf_(gPu[0]);
            float gf = sigmoidf_(gPu[64 * 8]);
            float gc = tanhf_  (gPu[128 * 8]);
            float go = sigmoidf_(gPu[192 * 8]);
            c0 = fmaf(gf, c0, gi * gc);
            *(float*)(ph0w + wbB) = go * tanhf_(c0);          // h0_{t+1}
        }
        if (tid < 48 && t + 2 < TT)
            *(float*)(pxw + (wbB >> 2)) = xreg;               // x_{t+2}
        __syncthreads();

        rbB = wbB;
    }

    // ================= FC head: h1_{TT-1} lives in buffer TT&1 = 0 =================
    if (tid < 256) {
        const int row = tid >> 5;
        const int m   = tid & 31;
        float acc2 = bfc1[m];
#pragma unroll 8
        for (int k = 0; k < HH; k++) {
            int p = k >> 1;
            float hv = hT1[(TT & 1) * 512 + lidx(p) + row * 2 + (k & 1)];
            acc2 = fmaf(hv, Wfc1[m * HH + k], acc2);
        }
        acc2 = fmaxf(acc2, 0.0f) * Wfc2[m];
#pragma unroll
        for (int off = 16; off > 0; off >>= 1)
            acc2 += __shfl_down_sync(0xffffffffu, acc2, off);
        if (m == 0)
            out[b0_ + row] = acc2 + bfc2[0];
    }
}

extern "C" void kernel_launch(void* const* d_in, const int* in_sizes, int n_in,
                              void* d_out, int out_size) {
    const float* x    = (const float*)d_in[0];
    const float* Wih0 = (const float*)d_in[1];
    const float* Whh0 = (const float*)d_in[2];
    const float* bih0 = (const float*)d_in[3];
    const float* bhh0 = (const float*)d_in[4];
    const float* Wih1 = (const float*)d_in[5];
    const float* Whh1 = (const float*)d_in[6];
    const float* bih1 = (const float*)d_in[7];
    const float* bhh1 = (const float*)d_in[8];
    const float* Wfc1 = (const float*)d_in[9];
    const float* bfc1 = (const float*)d_in[10];
    const float* Wfc2 = (const float*)d_in[11];
    const float* bfc2 = (const float*)d_in[12];
    float* out = (float*)d_out;

    cudaFuncSetAttribute(lstm_net_kernel,
                         cudaFuncAttributeMaxDynamicSharedMemorySize, SMEM_BYTES);
    lstm_net_kernel<<<NCTA, NTH, SMEM_BYTES>>>(
        x, Wih0, Whh0, bih0, bhh0, Wih1, Whh1, bih1, bhh1,
        Wfc1, bfc1, Wfc2, bfc2, out);
}

// round 15
// speedup vs baseline: 1.0892x; 1.0233x over previous
#include <cuda_runtime.h>

#define BB   1024
#define TT   512
#define IN   6
#define HH   64
#define GG   256
#define RR   8
#define NTH  512
#define NCTA (BB / RR)

// smem offsets (floats)
#define OFF_WHH1 0            // pair layout: W2[(kp*GG+g)*2 + (k&1)], 16384
#define OFF_WA   16384        // Whh0 staging (pair layout) 16384
#define OFF_WB   32768        // Wih1 staging (pair layout) 16384
#define OFF_WX   49152        // Wih0 (pair) 1536
#define OFF_B0   50688        // 256
#define OFF_B1   50944        // 256
#define OFF_GSH1 51200        // 2048  [g][r]
#define OFF_GSHP 53248        // 2048
#define OFF_HT0  55296        // 2 bufs x 512
#define OFF_HT1  56320        // 2 bufs x 512
#define OFF_XT   57344        // 2 bufs x 128
#define SMEM_FLOATS 57600
#define SMEM_BYTES  (SMEM_FLOATS * 4)   // 230400

typedef unsigned long long u64;

__device__ __forceinline__ u64 ffma2(u64 a, u64 b, u64 c) {
    u64 d;
    asm("fma.rn.f32x2 %0, %1, %2, %3;" : "=l"(d) : "l"(a), "l"(b), "l"(c));
    return d;
}
__device__ __forceinline__ float hsum2(u64 a) {
    union { u64 u; float2 f; } cvt; cvt.u = a;
    return cvt.f.x + cvt.f.y;
}
__device__ __forceinline__ float tanhf_(float x) {
    float y; asm("tanh.approx.f32 %0, %1;" : "=f"(y) : "f"(x)); return y;
}
__device__ __forceinline__ float sigmoidf_(float x) {
    return fmaf(0.5f, tanhf_(0.5f * x), 0.5f);
}
// line-merged h index for k-pair p: pairs p and p+16 share a 128B line
__device__ __forceinline__ int lidx(int p) {
    return (p & 15) * 32 + (p >> 4) * 16;
}

__global__ void __launch_bounds__(NTH, 1)
lstm_net_kernel(const float* __restrict__ x,
                const float* __restrict__ Wih0, const float* __restrict__ Whh0,
                const float* __restrict__ bih0, const float* __restrict__ bhh0,
                const float* __restrict__ Wih1, const float* __restrict__ Whh1,
                const float* __restrict__ bih1, const float* __restrict__ bhh1,
                const float* __restrict__ Wfc1, const float* __restrict__ bfc1,
                const float* __restrict__ Wfc2, const float* __restrict__ bfc2,
                float* __restrict__ out) {
    extern __shared__ float s[];
    float* Whh1s = s + OFF_WHH1;
    float* WAs   = s + OFF_WA;
    float* WBs   = s + OFF_WB;
    float* WXs   = s + OFF_WX;
    float* b0s   = s + OFF_B0;
    float* b1s   = s + OFF_B1;
    float* gsh1  = s + OFF_GSH1;
    float* gshP  = s + OFF_GSHP;
    float* hT0   = s + OFF_HT0;
    float* hT1   = s + OFF_HT1;
    float* xT    = s + OFF_XT;

    const int tid  = threadIdx.x;
    const int lane = tid & 31;
    const int w    = tid >> 5;
    const int gl   = lane & 15;
    const int half = lane >> 4;      // k-half: kp in [half*16, half*16+16)
    const int g    = w * 16 + gl;    // gate column
    const int b0_  = blockIdx.x * RR;

    // ---- Stage weights (all pair layout) ----
    for (int i = tid; i < HH * GG; i += NTH) {
        int gg_ = i >> 6;
        int k   = i & 63;
        int dp  = ((k >> 1) * GG + gg_) * 2 + (k & 1);
        WAs[dp]   = Whh0[i];
        WBs[dp]   = Wih1[i];
        Whh1s[dp] = Whh1[i];
    }
    for (int i = tid; i < IN * GG; i += NTH) {
        int gg_ = i / IN;
        int k   = i - gg_ * IN;
        WXs[((k >> 1) * GG + gg_) * 2 + (k & 1)] = Wih0[i];
    }
    if (tid < GG) {
        b0s[tid] = bih0[tid] + bhh0[tid];
        b1s[tid] = bih1[tid] + bhh1[tid];
    }
    for (int i = tid; i < 2048; i += NTH) hT0[i] = 0.0f;   // zeros hT0+hT1

    // x staging role (tid < 48)
    const int xk = tid >> 3;
    const int xr = tid & 7;
    const float* xgp = x + (size_t)(b0_ + xr) * TT * IN + xk;
    float* xslot0 = xT + (xk >> 1) * 32 + xr * 2 + (xk & 1);
    float xreg = 0.0f;
    if (tid < 48) xreg = xgp[0];                           // x_0

    // update role
    const int uj = tid >> 3;      // 0..63
    const int ur = tid & 7;       // 0..7
    const int hix = lidx(uj >> 1) + ur * 2 + (uj & 1);
    float c0 = 0.0f, c1 = 0.0f;

    __syncthreads();

    // ---- Fill weight registers: Whh0 + Wih1 (this lane's k-half, col g) ----
    u64 wpr[16], w1r[16];
#pragma unroll
    for (int i = 0; i < 16; i++) {
        const int off = ((half * 16 + i) * GG + g) * 2;
        wpr[i] = *(const u64*)(WAs + off);
        w1r[i] = *(const u64*)(WBs + off);
    }
    u64 wxr[3] = {0ULL, 0ULL, 0ULL};
    if (half == 0) {
#pragma unroll
        for (int p = 0; p < 3; p++)
            wxr[p] = *(const u64*)(WXs + (p * GG + g) * 2);
    }
    const float bias0 = b0s[g];
    const float bias1 = b1s[g];

    // ---- hoisted pointers (all per-step arithmetic becomes imm offsets / XOR) ----
    const float* whp   = Whh1s + (half * 16 * GG + g) * 2;  // + i*GG*2 (imm)
    float* gsh1w = gsh1 + g * 8;
    float* gshPw = gshP + g * 8;
    const float* g1u = gsh1 + uj * 8 + ur;
    const float* gPu = gshP + uj * 8 + ur;
    const char* ph0 = (const char*)(hT0 + half * 16);       // + rbB
    const char* ph1 = (const char*)(hT1 + half * 16);
    const char* pxb = (const char*)xT;                      // x buf is 128 floats = 512B
    char* ph1w = (char*)(hT1 + hix);
    char* ph0w = (char*)(hT0 + hix);
    char* pxw  = (char*)xslot0;

    // publish x_0 into xT buf1 (scratch)
    if (tid < 48) xslot0[128] = xreg;
    __syncthreads();

    // ================= PROLOGUE: gates0_0 = bias0 + Wih0 @ x_0 =================
    {
        u64 accP[8] = {0,0,0,0,0,0,0,0};
        if (half == 0) {
#pragma unroll
            for (int p = 0; p < 3; p++) {
                const float* xp = xT + 128 + p * 32;
                ulonglong2 A = *(const ulonglong2*)(xp);
                ulonglong2 B = *(const ulonglong2*)(xp + 4);
                ulonglong2 C = *(const ulonglong2*)(xp + 8);
                ulonglong2 D = *(const ulonglong2*)(xp + 12);
                accP[0] = ffma2(A.x, wxr[p], accP[0]);
                accP[1] = ffma2(A.y, wxr[p], accP[1]);
                accP[2] = ffma2(B.x, wxr[p], accP[2]);
                accP[3] = ffma2(B.y, wxr[p], accP[3]);
                accP[4] = ffma2(C.x, wxr[p], accP[4]);
                accP[5] = ffma2(C.y, wxr[p], accP[5]);
                accP[6] = ffma2(D.x, wxr[p], accP[6]);
                accP[7] = ffma2(D.y, wxr[p], accP[7]);
            }
        }
        float sPv[8];
#pragma unroll
        for (int r = 0; r < 8; r++) sPv[r] = hsum2(accP[r]);
#pragma unroll
        for (int r = 0; r < 8; r++) sPv[r] += __shfl_down_sync(0xffffffffu, sPv[r], 16);
        if (half == 0) {
            *(float4*)(gshPw) =
                make_float4(sPv[0] + bias0, sPv[1] + bias0, sPv[2] + bias0, sPv[3] + bias0);
            *(float4*)(gshPw + 4) =
                make_float4(sPv[4] + bias0, sPv[5] + bias0, sPv[6] + bias0, sPv[7] + bias0);
        }
        if (tid < 48) xreg = xgp[1 * IN];   // x_1
        __syncthreads();

        float gi = sigmoidf_(gPu[0]);
        float gf = sigmoidf_(gPu[64 * 8]);
        float gc = tanhf_  (gPu[128 * 8]);
        float go = sigmoidf_(gPu[192 * 8]);
        c0 = fmaf(gf, c0, gi * gc);
        hT0[hix] = go * tanhf_(c0);                 // buf 0
        if (tid < 48) xslot0[0] = xreg;             // buf 0
        __syncthreads();
    }

    // ================= MAIN LOOP =================
    int rbB = 0;                 // read-buffer byte offset (h bufs: 0/2048)
    for (int t = 0; t < TT; t++) {
        const int wbB = rbB ^ 2048;

        if (tid < 48 && t + 2 < TT)
            xreg = xgp[(size_t)(t + 2) * IN];

        u64 acc1[8] = {0,0,0,0,0,0,0,0};   // layer-1 gates (t)
        u64 accP[8] = {0,0,0,0,0,0,0,0};   // layer-0 gates (t+1)

        const float* h0b = (const float*)(ph0 + rbB);
        const float* h1b = (const float*)(ph1 + rbB);
#pragma unroll
        for (int i = 0; i < 16; i++) {
            // h0 pair: feeds two register weight streams
            const float* p0 = h0b + i * 32;
            ulonglong2 A = *(const ulonglong2*)(p0);
            ulonglong2 B = *(const ulonglong2*)(p0 + 4);
            ulonglong2 C = *(const ulonglong2*)(p0 + 8);
            ulonglong2 D = *(const ulonglong2*)(p0 + 12);
            const u64 w1 = w1r[i], wp = wpr[i];
            acc1[0] = ffma2(A.x, w1, acc1[0]);  accP[0] = ffma2(A.x, wp, accP[0]);
            acc1[1] = ffma2(A.y, w1, acc1[1]);  accP[1] = ffma2(A.y, wp, accP[1]);
            acc1[2] = ffma2(B.x, w1, acc1[2]);  accP[2] = ffma2(B.x, wp, accP[2]);
            acc1[3] = ffma2(B.y, w1, acc1[3]);  accP[3] = ffma2(B.y, wp, accP[3]);
            acc1[4] = ffma2(C.x, w1, acc1[4]);  accP[4] = ffma2(C.x, wp, accP[4]);
            acc1[5] = ffma2(C.y, w1, acc1[5]);  accP[5] = ffma2(C.y, wp, accP[5]);
            acc1[6] = ffma2(D.x, w1, acc1[6]);  accP[6] = ffma2(D.x, wp, accP[6]);
            acc1[7] = ffma2(D.y, w1, acc1[7]);  accP[7] = ffma2(D.y, wp, accP[7]);

            // h1 pair: Whh1 from smem (pair layout, imm offset)
            const u64 wh = *(const u64*)(whp + i * (GG * 2));
            const float* p1 = h1b + i * 32;
            ulonglong2 E = *(const ulonglong2*)(p1);
            ulonglong2 F = *(const ulonglong2*)(p1 + 4);
            ulonglong2 Gq = *(const ulonglong2*)(p1 + 8);
            ulonglong2 Hq = *(const ulonglong2*)(p1 + 12);
            acc1[0] = ffma2(E.x,  wh, acc1[0]);
            acc1[1] = ffma2(E.y,  wh, acc1[1]);
            acc1[2] = ffma2(F.x,  wh, acc1[2]);
            acc1[3] = ffma2(F.y,  wh, acc1[3]);
            acc1[4] = ffma2(Gq.x, wh, acc1[4]);
            acc1[5] = ffma2(Gq.y, wh, acc1[5]);
            acc1[6] = ffma2(Hq.x, wh, acc1[6]);
            acc1[7] = ffma2(Hq.y, wh, acc1[7]);
        }
        if (half == 0) {      // accP += Wih0 @ x_{t+1}   (x buf: 512B ping-pong)
            const float* xb = (const float*)(pxb + (rbB >> 2));
#pragma unroll
            for (int p = 0; p < 3; p++) {
                const float* xp = xb + p * 32;
                ulonglong2 A = *(const ulonglong2*)(xp);
                ulonglong2 B = *(const ulonglong2*)(xp + 4);
                ulonglong2 C = *(const ulonglong2*)(xp + 8);
                ulonglong2 D = *(const ulonglong2*)(xp + 12);
                accP[0] = ffma2(A.x, wxr[p], accP[0]);
                accP[1] = ffma2(A.y, wxr[p], accP[1]);
                accP[2] = ffma2(B.x, wxr[p], accP[2]);
                accP[3] = ffma2(B.y, wxr[p], accP[3]);
                accP[4] = ffma2(C.x, wxr[p], accP[4]);
                accP[5] = ffma2(C.y, wxr[p], accP[5]);
                accP[6] = ffma2(D.x, wxr[p], accP[6]);
                accP[7] = ffma2(D.y, wxr[p], accP[7]);
            }
        }

        // combine k-halves in-warp, half0 stores final gates
        float s1v[8], sPv[8];
#pragma unroll
        for (int r = 0; r < 8; r++) { s1v[r] = hsum2(acc1[r]); sPv[r] = hsum2(accP[r]); }
#pragma unroll
        for (int r = 0; r < 8; r++) {
            s1v[r] += __shfl_down_sync(0xffffffffu, s1v[r], 16);
            sPv[r] += __shfl_down_sync(0xffffffffu, sPv[r], 16);
        }
        if (half == 0) {
            *(float4*)(gsh1w) =
                make_float4(s1v[0] + bias1, s1v[1] + bias1, s1v[2] + bias1, s1v[3] + bias1);
            *(float4*)(gsh1w + 4) =
                make_float4(s1v[4] + bias1, s1v[5] + bias1, s1v[6] + bias1, s1v[7] + bias1);
            *(float4*)(gshPw) =
                make_float4(sPv[0] + bias0, sPv[1] + bias0, sPv[2] + bias0, sPv[3] + bias0);
            *(float4*)(gshPw + 4) =
                make_float4(sPv[4] + bias0, sPv[5] + bias0, sPv[6] + bias0, sPv[7] + bias0);
        }
        __syncthreads();

        // ---------- PHASE 2: both cell updates ----------
        {
            float gi = sigmoidf_(g1u[0]);
            float gf = sigmoidf_(g1u[64 * 8]);
            float gc = tanhf_  (g1u[128 * 8]);
            float go = sigmoidf_(g1u[192 * 8]);
            c1 = fmaf(gf, c1, gi * gc);
            *(float*)(ph1w + wbB) = go * tanhf_(c1);          // h1_t
        }
        {
            float gi = sigmoidf_(gPu[0]);
            float gf = sigmoidf_(gPu[64 * 8]);
            float gc = tanhf_  (gPu[128 * 8]);
            float go = sigmoidf_(gPu[192 * 8]);
            c0 = fmaf(gf, c0, gi * gc);
            *(float*)(ph0w + wbB) = go * tanhf_(c0);          // h0_{t+1}
        }
        if (tid < 48 && t + 2 < TT)
            *(float*)(pxw + (wbB >> 2)) = xreg;               // x_{t+2}
        __syncthreads();

        rbB = wbB;
    }

    // ================= FC head: h1_{TT-1} lives in buffer TT&1 = 0 =================
    if (tid < 256) {
        const int row = tid >> 5;
        const int m   = tid & 31;
        float acc2 = bfc1[m];
#pragma unroll 8
        for (int k = 0; k < HH; k++) {
            int p = k >> 1;
            float hv = hT1[(TT & 1) * 512 + lidx(p) + row * 2 + (k & 1)];
            acc2 = fmaf(hv, Wfc1[m * HH + k], acc2);
        }
        acc2 = fmaxf(acc2, 0.0f) * Wfc2[m];
#pragma unroll
        for (int off = 16; off > 0; off >>= 1)
            acc2 += __shfl_down_sync(0xffffffffu, acc2, off);
        if (m == 0)
            out[b0_ + row] = acc2 + bfc2[0];
    }
}

extern "C" void kernel_launch(void* const* d_in, const int* in_sizes, int n_in,
                              void* d_out, int out_size) {
    const float* x    = (const float*)d_in[0];
    const float* Wih0 = (const float*)d_in[1];
    const float* Whh0 = (const float*)d_in[2];
    const float* bih0 = (const float*)d_in[3];
    const float* bhh0 = (const float*)d_in[4];
    const float* Wih1 = (const float*)d_in[5];
    const float* Whh1 = (const float*)d_in[6];
    const float* bih1 = (const float*)d_in[7];
    const float* bhh1 = (const float*)d_in[8];
    const float* Wfc1 = (const float*)d_in[9];
    const float* bfc1 = (const float*)d_in[10];
    const float* Wfc2 = (const float*)d_in[11];
    const float* bfc2 = (const float*)d_in[12];
    float* out = (float*)d_out;

    cudaFuncSetAttribute(lstm_net_kernel,
                         cudaFuncAttributeMaxDynamicSharedMemorySize, SMEM_BYTES);
    lstm_net_kernel<<<NCTA, NTH, SMEM_BYTES>>>(
        x, Wih0, Whh0, bih0, bhh0, Wih1, Whh1, bih1, bhh1,
        Wfc1, bfc1, Wfc2, bfc2, out);
}